// round 14
// baseline (speedup 1.0000x reference)
#include <cuda_runtime.h>

// Stacked LSTM: B=64, T=512, D=256, H=512, 3 layers. fp32.
// R14: TWO independent recurrence chains (batch rows 0-31 / 32-63), each with
// its own 128-block grid barrier. 256 blocks x 256 threads, ~101KB smem =>
// 2 blocks (one per chain) co-resident per SM: one chain's barrier/memory
// stalls are covered by the other chain's compute.
// Per block: 4 hidden units (16 z-cols) x 32 batch rows, K = D+H or 2H,
// 8-warp k-split, packed f32x2 FFMA, weights resident in smem,
// single-buffered 128-k A chunks, x-region chunks computed pre-wait.

#define Bsz 64
#define Tsz 512
#define Dsz 256
#define Hsz 512
#define Gsz 2048
#define NBLK 256
#define NTHR 256

typedef unsigned long long u64;

// smem floats: w_s [1024][16] 16384 | a_s [32][132] 4224 | zred [8][32][18] 4608 | bias 16
#define SM_WS   0
#define SM_AS   16384
#define SM_ZRED (16384 + 4224)
#define SM_BIAS (16384 + 4224 + 4608)
#define SMEM_FLOATS (SM_BIAS + 16)
#define SMEM_BYTES (SMEM_FLOATS * 4)      // ~100.9 KB -> 2 blocks/SM
#define ASTRIDE 132

__device__ float g_seqA[(size_t)Bsz * Tsz * Hsz];
__device__ float g_seqB[(size_t)Bsz * Tsz * Hsz];
__device__ float g_hbuf[2][Bsz * Hsz];
__device__ unsigned g_count[64];   // [grp*32]: separate cache lines
__device__ unsigned g_gen[64];     // [grp*32]

// ---- split-phase per-group grid barrier (128 blocks; snapshot-based) ----
__device__ __forceinline__ void bar_arrive(unsigned* s_my, int grp) {
    __syncthreads();
    if (threadIdx.x == 0) {
        unsigned* cnt = &g_count[grp * 32];
        unsigned* gen = &g_gen[grp * 32];
        unsigned my;
        asm volatile("ld.relaxed.gpu.u32 %0, [%1];" : "=r"(my) : "l"(gen));
        *s_my = my;
        __threadfence();
        unsigned old = atomicAdd(cnt, 1u);
        if (old == 127u) {
            *cnt = 0;
            __threadfence();
            asm volatile("st.release.gpu.u32 [%0], %1;" :: "l"(gen), "r"(my + 1u));
        }
    }
}
__device__ __forceinline__ void bar_wait(unsigned* s_my, int grp) {
    if (threadIdx.x == 0) {
        unsigned* gen = &g_gen[grp * 32];
        unsigned my = *s_my, g;
        do {
            asm volatile("ld.acquire.gpu.u32 %0, [%1];" : "=r"(g) : "l"(gen));
        } while (g == my);
    }
    __syncthreads();
}

__device__ __forceinline__ float fsig(float x) {
    return __fdividef(1.0f, 1.0f + __expf(-x));
}
__device__ __forceinline__ float ftanh(float x) {
    float e = __expf(2.0f * x);
    return 1.0f - __fdividef(2.0f, e + 1.0f);
}
__device__ __forceinline__ void fma2(u64& d, u64 a, u64 b) {
    asm("fma.rn.f32x2 %0, %1, %2, %0;" : "+l"(d) : "l"(a), "l"(b));
}
__device__ __forceinline__ u64 rep2(float x) {
    u64 r;
    asm("mov.b64 %0, {%1, %1};" : "=l"(r) : "f"(x));
    return r;
}

extern "C" __global__ void __launch_bounds__(NTHR, 2)
lstm_kernel(const float* __restrict__ x0,
            const float* __restrict__ W0, const float* __restrict__ U0, const float* __restrict__ b0,
            const float* __restrict__ W1, const float* __restrict__ U1, const float* __restrict__ b1,
            const float* __restrict__ W2, const float* __restrict__ U2, const float* __restrict__ b2,
            float* __restrict__ out)
{
    extern __shared__ float smem[];
    float* w_s    = smem + SM_WS;     // [k][16]
    float* a_s    = smem + SM_AS;     // [32][ASTRIDE]
    float* zred   = smem + SM_ZRED;   // [8][32][18]
    float* bias_s = smem + SM_BIAS;   // [16]
    float* zpart  = a_s;              // gather scratch [4][128] (a_s idle then)
    __shared__ unsigned s_my;

    const int tid  = threadIdx.x;
    const int bc   = blockIdx.x;
    const int grp  = bc >> 7;          // 0/1: batch rows [grp*32, grp*32+32)
    const int ubc  = bc & 127;         // unit block
    const int j0   = ubc * 4;
    const int row0 = grp * 32;
    // compute mapping: warp = k-group (16 k per 128-k chunk)
    const int ks   = tid >> 5;         // 0..7
    const int lane = tid & 31;
    const int rg   = lane >> 2;        // 0..7 : local rows rg + 8u, u<4
    const int cq   = lane & 3;         // 0..3 : cols cq*4 .. +3
    // staging mapping (32 rows x 128 k, 256 threads x 4 float4)
    const int sk4  = lane * 4;         // 0..124
    const int srow = tid >> 5;         // local rows srow + 8r, r<4
    // gate mapping (tid<128); pre-gather (tid>=128) uses same decode
    const int gb = (tid & 127) >> 2;   // local batch row 0..31
    const int gj = tid & 3;

    for (int layer = 0; layer < 3; layer++) {
        const float* Wl = (layer == 0) ? W0 : ((layer == 1) ? W1 : W2);
        const float* Ul = (layer == 0) ? U0 : ((layer == 1) ? U1 : U2);
        const float* bl = (layer == 0) ? b0 : ((layer == 1) ? b1 : b2);
        const float* xsrc = (layer == 0) ? x0 : ((layer == 1) ? g_seqA : g_seqB);
        float* seqout = (layer == 0) ? g_seqA : ((layer == 1) ? g_seqB : (float*)0);
        const int K_in = (layer == 0) ? Dsz : Hsz;
        const int Ktot = K_in + Hsz;        // 768 or 1024
        const int nch  = Ktot >> 7;         // 6 or 8
        const int nxc  = K_in >> 7;         // 2 or 4 (x-region chunks)

        // ---- weights resident in smem (once per layer) ----
        for (int idx = tid; idx < Ktot * 4; idx += NTHR) {
            int gk = idx >> 2, p = idx & 3;
            const float* wrow = (gk < K_in) ? (Wl + (size_t)gk * Gsz)
                                            : (Ul + (size_t)(gk - K_in) * Gsz);
            *(float4*)&w_s[gk * 16 + p * 4] = *(const float4*)(wrow + p * Hsz + j0);
        }
        if (tid < 16) bias_s[tid] = bl[(tid >> 2) * Hsz + j0 + (tid & 3)];
        float c_reg = 0.0f, hval = 0.0f;
        if (tid < 128) g_hbuf[0][(row0 + gb) * Hsz + j0 + gj] = 0.0f;
        int cur = 0;
        bar_arrive(&s_my, grp);   // publish zeroed h_0 (this group)

        float4 st[4];
        #define LDG_CHUNK(TT, CI)                                                     \
            do {                                                                      \
                int kb_ = (CI) << 7;                                                  \
                if (kb_ < K_in) {                                                     \
                    _Pragma("unroll")                                                 \
                    for (int r_ = 0; r_ < 4; r_++)                                    \
                        st[r_] = *(const float4*)(xsrc +                              \
                            ((size_t)(row0 + srow + 8 * r_) * Tsz + (TT)) * K_in + kb_ + sk4); \
                } else {                                                              \
                    const float* s_ = hsrc + (kb_ - K_in) + sk4;                      \
                    _Pragma("unroll")                                                 \
                    for (int r_ = 0; r_ < 4; r_++)                                    \
                        st[r_] = *(const float4*)(s_ + (row0 + srow + 8 * r_) * Hsz); \
                }                                                                     \
            } while (0)

        #define STS_CHUNK()                                                           \
            do {                                                                      \
                _Pragma("unroll")                                                     \
                for (int r_ = 0; r_ < 4; r_++)                                        \
                    *(float4*)&a_s[(srow + 8 * r_) * ASTRIDE + sk4] = st[r_];         \
            } while (0)

        // this warp's 16-k slice of chunk CI (single a_s buffer)
        #define COMPUTE_CHUNK(CI)                                                     \
            do {                                                                      \
                const float* wb = w_s + (((CI) << 7) + ks * 16) * 16 + cq * 4;        \
                const float* ab = a_s + ks * 16;                                      \
                _Pragma("unroll")                                                     \
                for (int kq = 0; kq < 4; kq++) {                                      \
                    float av[4][4];                                                   \
                    _Pragma("unroll")                                                 \
                    for (int u = 0; u < 4; u++)                                       \
                        *(float4*)av[u] = *(const float4*)&ab[(rg + 8 * u) * ASTRIDE + kq * 4]; \
                    _Pragma("unroll")                                                 \
                    for (int j = 0; j < 4; j++) {                                     \
                        ulonglong2 w2 = *(const ulonglong2*)(wb + (kq * 4 + j) * 16); \
                        _Pragma("unroll")                                             \
                        for (int u = 0; u < 4; u++) {                                 \
                            u64 ar = rep2(av[u][j]);                                  \
                            fma2(acc[u][0], ar, w2.x);                                \
                            fma2(acc[u][1], ar, w2.y);                                \
                        }                                                             \
                    }                                                                 \
                }                                                                     \
            } while (0)

        {
            const float* hsrc = g_hbuf[0];
            LDG_CHUNK(0, 0);   // step-0 chunk 0 (x region)
            (void)hsrc;
        }

        for (int t = 0; t < Tsz; t++) {
            const float* hsrc = g_hbuf[cur];
            u64 acc[4][2] = {};

            // ---- x phase (overlaps this group's barrier arrival spread) ----
            for (int ci = 0; ci < nxc; ci++) {
                STS_CHUNK();
                if (ci + 1 < nxc) LDG_CHUNK(t, ci + 1);   // overlaps compute(ci)
                __syncthreads();
                COMPUTE_CHUNK(ci);
                if (ci + 1 < nxc) __syncthreads();
            }

            // ---- wait for this group's h_t, then h phase ----
            bar_wait(&s_my, grp);   // ends with __syncthreads
            for (int ci = nxc; ci < nch; ci++) {
                if (ci == nxc) LDG_CHUNK(t, ci);
                STS_CHUNK();
                if (ci + 1 < nch) LDG_CHUNK(t, ci + 1);
                __syncthreads();
                COMPUTE_CHUNK(ci);
                if (ci + 1 < nch) __syncthreads();
            }

            // ---- k-split partials ----
            #pragma unroll
            for (int u = 0; u < 4; u++)
                #pragma unroll
                for (int p = 0; p < 2; p++)
                    *(float2*)&zred[ks * 576 + (rg + 8 * u) * 18 + cq * 4 + p * 2] =
                        *(float2*)&acc[u][p];
            __syncthreads();

            // ---- split gather: tid>=128 pre-sums k-groups 4..7 ----
            if (tid >= 128) {
                #pragma unroll
                for (int g = 0; g < 4; g++) {
                    int o = gb * 18 + g * 4 + gj;
                    float s = zred[4 * 576 + o] + zred[5 * 576 + o]
                            + zred[6 * 576 + o] + zred[7 * 576 + o];
                    zpart[g * 128 + (tid - 128)] = s;
                }
            }
            __syncthreads();

            // ---- gates (tid<128: one thread per (local b, j)) ----
            if (tid < 128) {
                float z[4];
                #pragma unroll
                for (int g = 0; g < 4; g++) {
                    int o = gb * 18 + g * 4 + gj;
                    z[g] = bias_s[g * 4 + gj] + zpart[g * 128 + tid]
                         + zred[o] + zred[576 + o] + zred[1152 + o] + zred[1728 + o];
                }
                float ig = fsig(z[0]);
                float fg = fsig(z[1]);
                float gg = ftanh(z[2]);
                float og = fsig(z[3]);
                c_reg = fg * c_reg + ig * gg;
                hval  = og * ftanh(c_reg);
                g_hbuf[cur ^ 1][(row0 + gb) * Hsz + j0 + gj] = hval;
                if (seqout)
                    seqout[((size_t)(row0 + gb) * Tsz + t) * Hsz + j0 + gj] = hval;
            }
            cur ^= 1;

            bar_arrive(&s_my, grp);               // publish h_{t+1} + seq row
            if (t + 1 < Tsz) LDG_CHUNK(t + 1, 0); // prefetch next x chunk 0
        }
        bar_wait(&s_my, grp);   // this group's layer complete

        // ---- layer finals. Output: [out(=h2) | h0 | c0 | h1 | c1 | h2 | c2] ----
        if (tid < 128) {
            size_t off = (size_t)(row0 + gb) * Hsz + j0 + gj;
            const size_t S = (size_t)Bsz * Hsz;
            if (layer == 0)      { out[1 * S + off] = hval; out[2 * S + off] = c_reg; }
            else if (layer == 1) { out[3 * S + off] = hval; out[4 * S + off] = c_reg; }
            else                 { out[off] = hval; out[5 * S + off] = hval; out[6 * S + off] = c_reg; }
        }
        #undef LDG_CHUNK
        #undef STS_CHUNK
        #undef COMPUTE_CHUNK
    }
}

extern "C" void kernel_launch(void* const* d_in, const int* in_sizes, int n_in,
                              void* d_out, int out_size) {
    (void)in_sizes; (void)n_in; (void)out_size;
    static int attr_done = 0;
    if (!attr_done) {
        cudaFuncSetAttribute(lstm_kernel,
                             cudaFuncAttributeMaxDynamicSharedMemorySize, SMEM_BYTES);
        attr_done = 1;
    }
    lstm_kernel<<<NBLK, NTHR, SMEM_BYTES>>>(
        (const float*)d_in[0],
        (const float*)d_in[1], (const float*)d_in[2], (const float*)d_in[3],
        (const float*)d_in[4], (const float*)d_in[5], (const float*)d_in[6],
        (const float*)d_in[7], (const float*)d_in[8], (const float*)d_in[9],
        (float*)d_out);
}

// round 15
// speedup vs baseline: 1.0045x; 1.0045x over previous
#include <cuda_runtime.h>

// Stacked LSTM: B=64, T=512, D=256, H=512, 3 layers. fp32.
// R13 skeleton (persistent, 128 blocks x 512 threads, split-phase single-
// counter grid barrier, weights resident in smem, double-buffered 128-k
// chunks, x-chunks computed between arrive and wait).
// R15 delta: LDS-minimizing compute mapping. Warp = (k-group ks<8, col-half
// ch<2); all lanes share the warp's 8 weight cols => w-loads are uniform
// (broadcast, 1-cyc crossbar). Thread tile = rows {lane, lane+32} x 8 cols
// (conflict-free float4 a-loads at stride 132). k-split 16 -> 8.

#define Bsz 64
#define Tsz 512
#define Dsz 256
#define Hsz 512
#define Gsz 2048
#define NBLK 128
#define NTHR 512

typedef unsigned long long u64;

// smem floats: w_s [1024][16] 16384 | a_s [2][64][132] 16896 | zred [8][64][18] 9216 | bias 16
#define SM_WS   0
#define SM_AS   16384
#define SM_ZRED (16384 + 16896)
#define SM_BIAS (16384 + 16896 + 9216)
#define SMEM_FLOATS (SM_BIAS + 16)
#define SMEM_BYTES (SMEM_FLOATS * 4)
#define ASTRIDE 132
#define ABUF (64 * ASTRIDE)

__device__ float g_seqA[(size_t)Bsz * Tsz * Hsz];
__device__ float g_seqB[(size_t)Bsz * Tsz * Hsz];
__device__ float g_hbuf[2][Bsz * Hsz];
__device__ unsigned g_count = 0;
__device__ unsigned g_gen = 0;

// ---- split-phase grid barrier (single counter; snapshot-based) ----
__device__ __forceinline__ void bar_arrive(unsigned* s_my) {
    __syncthreads();
    if (threadIdx.x == 0) {
        unsigned my;
        asm volatile("ld.relaxed.gpu.u32 %0, [%1];" : "=r"(my) : "l"(&g_gen));
        *s_my = my;
        __threadfence();
        unsigned old = atomicAdd(&g_count, 1u);
        if (old == NBLK - 1) {
            g_count = 0;
            __threadfence();
            asm volatile("st.release.gpu.u32 [%0], %1;" :: "l"(&g_gen), "r"(my + 1u));
        }
    }
}
__device__ __forceinline__ void bar_wait(unsigned* s_my) {
    if (threadIdx.x == 0) {
        unsigned my = *s_my, g;
        do {
            asm volatile("ld.acquire.gpu.u32 %0, [%1];" : "=r"(g) : "l"(&g_gen));
        } while (g == my);
    }
    __syncthreads();
}

__device__ __forceinline__ float fsig(float x) {
    return __fdividef(1.0f, 1.0f + __expf(-x));
}
__device__ __forceinline__ float ftanh(float x) {
    float e = __expf(2.0f * x);
    return 1.0f - __fdividef(2.0f, e + 1.0f);
}
__device__ __forceinline__ void fma2(u64& d, u64 a, u64 b) {
    asm("fma.rn.f32x2 %0, %1, %2, %0;" : "+l"(d) : "l"(a), "l"(b));
}
__device__ __forceinline__ u64 rep2(float x) {
    u64 r;
    asm("mov.b64 %0, {%1, %1};" : "=l"(r) : "f"(x));
    return r;
}

extern "C" __global__ void __launch_bounds__(NTHR, 1)
lstm_kernel(const float* __restrict__ x0,
            const float* __restrict__ W0, const float* __restrict__ U0, const float* __restrict__ b0,
            const float* __restrict__ W1, const float* __restrict__ U1, const float* __restrict__ b1,
            const float* __restrict__ W2, const float* __restrict__ U2, const float* __restrict__ b2,
            float* __restrict__ out)
{
    extern __shared__ float smem[];
    float* w_s    = smem + SM_WS;     // [k][16]
    float* a_s    = smem + SM_AS;     // [2][64][ASTRIDE]
    float* zred   = smem + SM_ZRED;   // [8][64][18]
    float* bias_s = smem + SM_BIAS;   // [16]
    float* zpart  = a_s;              // gather scratch [4][256] (a_s idle then)
    __shared__ unsigned s_my;

    const int tid = threadIdx.x;
    const int bc  = blockIdx.x;
    const int j0  = bc * 4;
    // compute mapping: warp = (k-group, col-half); thread rows {lane, lane+32}
    const int wid  = tid >> 5;
    const int ks   = wid >> 1;        // 0..7 : k-slice ks*16..+16 per 128-chunk
    const int ch   = wid & 1;         // 0..1 : cols ch*8..+7
    const int lane = tid & 31;
    // staging mapping (128-k chunk: 64 rows x 128 k, 512 threads x 4 float4)
    const int sk4  = (tid & 31) * 4;  // 0..124
    const int srow = tid >> 5;        // rows srow + 16*r, r<4
    // gate mapping
    const int gb = (tid & 255) >> 2;
    const int gj = tid & 3;

    for (int layer = 0; layer < 3; layer++) {
        const float* Wl = (layer == 0) ? W0 : ((layer == 1) ? W1 : W2);
        const float* Ul = (layer == 0) ? U0 : ((layer == 1) ? U1 : U2);
        const float* bl = (layer == 0) ? b0 : ((layer == 1) ? b1 : b2);
        const float* xsrc = (layer == 0) ? x0 : ((layer == 1) ? g_seqA : g_seqB);
        float* seqout = (layer == 0) ? g_seqA : ((layer == 1) ? g_seqB : (float*)0);
        const int K_in = (layer == 0) ? Dsz : Hsz;
        const int Ktot = K_in + Hsz;        // 768 or 1024
        const int nch  = Ktot >> 7;         // 6 or 8 chunks
        const int nxc  = K_in >> 7;         // x-region chunks: 2 or 4

        // ---- weights resident in smem (once per layer) ----
        for (int idx = tid; idx < Ktot * 4; idx += NTHR) {
            int gk = idx >> 2, p = idx & 3;
            const float* wrow = (gk < K_in) ? (Wl + (size_t)gk * Gsz)
                                            : (Ul + (size_t)(gk - K_in) * Gsz);
            *(float4*)&w_s[gk * 16 + p * 4] = *(const float4*)(wrow + p * Hsz + j0);
        }
        if (tid < 16) bias_s[tid] = bl[(tid >> 2) * Hsz + j0 + (tid & 3)];
        float c_reg = 0.0f, hval = 0.0f;
        if (tid < 256) g_hbuf[0][gb * Hsz + j0 + gj] = 0.0f;
        int cur = 0;
        bar_arrive(&s_my);   // publish zeroed h_0

        float4 st[4];
        #define LDG_CHUNK(TT, CI)                                                     \
            do {                                                                      \
                int kb_ = (CI) << 7;                                                  \
                if (kb_ < K_in) {                                                     \
                    const float* s_ = xsrc + (size_t)(TT) * K_in + kb_ + sk4;         \
                    _Pragma("unroll")                                                 \
                    for (int r_ = 0; r_ < 4; r_++)                                    \
                        st[r_] = *(const float4*)(s_ + (size_t)(srow + 16 * r_) * Tsz * K_in); \
                } else {                                                              \
                    const float* s_ = hsrc + (kb_ - K_in) + sk4;                      \
                    _Pragma("unroll")                                                 \
                    for (int r_ = 0; r_ < 4; r_++)                                    \
                        st[r_] = *(const float4*)(s_ + (srow + 16 * r_) * Hsz);       \
                }                                                                     \
            } while (0)

        #define STS_CHUNK(BUF)                                                        \
            do {                                                                      \
                float* ad_ = a_s + (BUF) * ABUF;                                      \
                _Pragma("unroll")                                                     \
                for (int r_ = 0; r_ < 4; r_++)                                        \
                    *(float4*)&ad_[(srow + 16 * r_) * ASTRIDE + sk4] = st[r_];        \
            } while (0)

        // warp (ks, ch): 16-k slice of chunk CI; rows {lane, lane+32}, 8 cols.
        // w-loads are warp-uniform (broadcast); a-loads conflict-free float4.
        #define COMPUTE_CHUNK(BUF, CI)                                                \
            do {                                                                      \
                const float* wb = w_s + (((CI) << 7) + ks * 16) * 16 + ch * 8;        \
                const float* ab = a_s + (BUF) * ABUF + ks * 16;                       \
                _Pragma("unroll")                                                     \
                for (int kq = 0; kq < 4; kq++) {                                      \
                    float4 a0 = *(const float4*)&ab[lane * ASTRIDE + kq * 4];         \
                    float4 a1 = *(const float4*)&ab[(lane + 32) * ASTRIDE + kq * 4];  \
                    _Pragma("unroll")                                                 \
                    for (int j = 0; j < 4; j++) {                                     \
                        const float* wr = wb + (kq * 4 + j) * 16;                     \
                        ulonglong2 wlo = *(const ulonglong2*)wr;                      \
                        ulonglong2 whi = *(const ulonglong2*)(wr + 4);                \
                        u64 ar0 = rep2(((const float*)&a0)[j]);                       \
                        u64 ar1 = rep2(((const float*)&a1)[j]);                       \
                        fma2(acc[0][0], ar0, wlo.x); fma2(acc[0][1], ar0, wlo.y);     \
                        fma2(acc[0][2], ar0, whi.x); fma2(acc[0][3], ar0, whi.y);     \
                        fma2(acc[1][0], ar1, wlo.x); fma2(acc[1][1], ar1, wlo.y);     \
                        fma2(acc[1][2], ar1, whi.x); fma2(acc[1][3], ar1, whi.y);     \
                    }                                                                 \
                }                                                                     \
            } while (0)

        {
            const float* hsrc = g_hbuf[0];
            LDG_CHUNK(0, 0);   // step-0 chunk 0 (x region, barrier-independent)
            (void)hsrc;
        }

        for (int t = 0; t < Tsz; t++) {
            const float* hsrc = g_hbuf[cur];
            u64 acc[2][4] = {};

            // ---- x phase (overlaps other blocks' arrival) ----
            STS_CHUNK(0);
            LDG_CHUNK(t, 1);
            __syncthreads();
            for (int ci = 0; ci < nxc; ci++) {
                if (ci + 1 < nxc) {
                    STS_CHUNK((ci + 1) & 1);
                    if (ci + 2 < nxc) LDG_CHUNK(t, ci + 2);
                }
                COMPUTE_CHUNK(ci & 1, ci);
                if (ci + 1 < nxc) __syncthreads();
            }

            // ---- wait for h_t, then h phase ----
            bar_wait(&s_my);   // ends with __syncthreads
            LDG_CHUNK(t, nxc);
            STS_CHUNK(nxc & 1);
            LDG_CHUNK(t, nxc + 1);
            __syncthreads();
            for (int ci = nxc; ci < nch; ci++) {
                if (ci + 1 < nch) {
                    STS_CHUNK((ci + 1) & 1);
                    if (ci + 2 < nch) LDG_CHUNK(t, ci + 2);
                }
                COMPUTE_CHUNK(ci & 1, ci);
                if (ci + 1 < nch) __syncthreads();
            }

            // ---- k-split partials: rows {lane, lane+32}, cols ch*8.. ----
            #pragma unroll
            for (int u = 0; u < 2; u++) {
                int row = lane + 32 * u;
                #pragma unroll
                for (int p = 0; p < 4; p++)
                    *(float2*)&zred[ks * 1152 + row * 18 + ch * 8 + p * 2] =
                        *(float2*)&acc[u][p];
            }
            __syncthreads();

            // ---- split gather: upper half pre-sums k-groups 4..7 ----
            if (tid >= 256) {
                #pragma unroll
                for (int g = 0; g < 4; g++) {
                    int o = gb * 18 + g * 4 + gj;
                    float s = zred[4 * 1152 + o] + zred[5 * 1152 + o]
                            + zred[6 * 1152 + o] + zred[7 * 1152 + o];
                    zpart[g * 256 + (tid - 256)] = s;
                }
            }
            __syncthreads();

            // ---- gates (tid < 256: one thread per (b, j)) ----
            if (tid < 256) {
                float z[4];
                #pragma unroll
                for (int g = 0; g < 4; g++) {
                    int o = gb * 18 + g * 4 + gj;
                    z[g] = bias_s[g * 4 + gj] + zpart[g * 256 + tid]
                         + zred[o] + zred[1152 + o] + zred[2304 + o] + zred[3456 + o];
                }
                float ig = fsig(z[0]);
                float fg = fsig(z[1]);
                float gg = ftanh(z[2]);
                float og = fsig(z[3]);
                c_reg = fg * c_reg + ig * gg;
                hval  = og * ftanh(c_reg);
                g_hbuf[cur ^ 1][gb * Hsz + j0 + gj] = hval;
                if (seqout)
                    seqout[((size_t)(gb * Tsz + t)) * Hsz + j0 + gj] = hval;
            }
            cur ^= 1;

            bar_arrive(&s_my);                     // publish h_{t+1} (+seq row)
            if (t + 1 < Tsz) LDG_CHUNK(t + 1, 0);  // prefetch next x chunk 0
        }
        bar_wait(&s_my);   // layer complete everywhere

        // ---- layer finals. Output: [out(=h2) | h0 | c0 | h1 | c1 | h2 | c2] ----
        if (tid < 256) {
            size_t off = (size_t)gb * Hsz + j0 + gj;
            const size_t S = (size_t)Bsz * Hsz;
            if (layer == 0)      { out[1 * S + off] = hval; out[2 * S + off] = c_reg; }
            else if (layer == 1) { out[3 * S + off] = hval; out[4 * S + off] = c_reg; }
            else                 { out[off] = hval; out[5 * S + off] = hval; out[6 * S + off] = c_reg; }
        }
        #undef LDG_CHUNK
        #undef STS_CHUNK
        #undef COMPUTE_CHUNK
    }
}

extern "C" void kernel_launch(void* const* d_in, const int* in_sizes, int n_in,
                              void* d_out, int out_size) {
    (void)in_sizes; (void)n_in; (void)out_size;
    static int attr_done = 0;
    if (!attr_done) {
        cudaFuncSetAttribute(lstm_kernel,
                             cudaFuncAttributeMaxDynamicSharedMemorySize, SMEM_BYTES);
        attr_done = 1;
    }
    lstm_kernel<<<NBLK, NTHR, SMEM_BYTES>>>(
        (const float*)d_in[0],
        (const float*)d_in[1], (const float*)d_in[2], (const float*)d_in[3],
        (const float*)d_in[4], (const float*)d_in[5], (const float*)d_in[6],
        (const float*)d_in[7], (const float*)d_in[8], (const float*)d_in[9],
        (float*)d_out);
}